// round 1
// baseline (speedup 1.0000x reference)
#include <cuda_runtime.h>

// MSD block: 12 dilated 3x3 convs (reflect pad, ReLU), channels concatenated.
// Output buffer d_out holds the full (4, 25, 512, 512) concat tensor; each layer
// kernel reads channels [0, n_in) and writes channels [n_in, n_in+2) in place.

#define Bdim 4
#define Hdim 512
#define Wdim 512
#define C_TOTAL 25
#define CS (Hdim * Wdim)

typedef unsigned long long u64;

__device__ __forceinline__ void fma2(u64& d, u64 a, u64 b) {
    asm("fma.rn.f32x2 %0, %1, %2, %0;" : "+l"(d) : "l"(a), "l"(b));
}
__device__ __forceinline__ u64 dup2(float v) {
    u64 r; asm("mov.b64 %0, {%1, %1};" : "=l"(r) : "f"(v)); return r;
}
__device__ __forceinline__ u64 pack2(float lo, float hi) {
    u64 r; asm("mov.b64 %0, {%1, %2};" : "=l"(r) : "f"(lo), "f"(hi)); return r;
}
__device__ __forceinline__ void unpack2(u64 v, float& lo, float& hi) {
    asm("mov.b64 {%0, %1}, %2;" : "=f"(lo), "=f"(hi) : "l"(v));
}

// Input-row-stationary conv body: thread owns output column w, rows [r0, r0+R).
// For each input channel, sweep input rows r0-D .. r0+R-1+D once; each row's 3
// kw-taps (w-D, w, w+D) feed up to 3 kh accumulator rows x 2 packed out channels.
template<int N_IN, int D, int R, bool REFL>
__device__ __forceinline__ void conv_body(const float* __restrict__ buf,
                                          float* __restrict__ outp,
                                          const u64* __restrict__ ws2,
                                          u64 bias2, int b, int r0, int w) {
    int wl = w - D; if (wl < 0) wl = -wl;                      // reflect cols
    int wr = w + D; if (wr >= Wdim) wr = 2 * Wdim - 2 - wr;

    u64 acc[R];
    #pragma unroll
    for (int m = 0; m < R; ++m) acc[m] = bias2;

    #pragma unroll 1
    for (int ic = 0; ic < N_IN; ++ic) {
        const float* plane = buf + ((size_t)b * C_TOTAL + ic) * CS;
        const u64* wrow = ws2 + ic * 9;
        u64 w00 = wrow[0], w01 = wrow[1], w02 = wrow[2];
        u64 w10 = wrow[3], w11 = wrow[4], w12 = wrow[5];
        u64 w20 = wrow[6], w21 = wrow[7], w22 = wrow[8];
        #pragma unroll
        for (int j = 0; j < R + 2 * D; ++j) {
            int x = r0 - D + j;
            int xr = x;
            if (REFL) {
                if (x < 0) xr = -x;
                else if (x >= Hdim) xr = 2 * Hdim - 2 - x;
            }
            const float* row = plane + (size_t)xr * Wdim;
            u64 vl = dup2(__ldg(row + wl));
            u64 vc = dup2(__ldg(row + w));
            u64 vr = dup2(__ldg(row + wr));
            // kh=0 contributes to out row m=j ; kh=1 -> m=j-D ; kh=2 -> m=j-2D
            if (j < R) {
                fma2(acc[j], w00, vl); fma2(acc[j], w01, vc); fma2(acc[j], w02, vr);
            }
            if (j >= D && j < R + D) {
                fma2(acc[j - D], w10, vl); fma2(acc[j - D], w11, vc); fma2(acc[j - D], w12, vr);
            }
            if (j >= 2 * D) {   // j - 2D < R always holds since j < R + 2D
                fma2(acc[j - 2 * D], w20, vl); fma2(acc[j - 2 * D], w21, vc); fma2(acc[j - 2 * D], w22, vr);
            }
        }
    }

    float* o0 = outp + ((size_t)b * C_TOTAL + N_IN) * CS + (size_t)r0 * Wdim + w;
    #pragma unroll
    for (int m = 0; m < R; ++m) {
        float lo, hi; unpack2(acc[m], lo, hi);
        o0[(size_t)m * Wdim]      = fmaxf(lo, 0.f);
        o0[CS + (size_t)m * Wdim] = fmaxf(hi, 0.f);
    }
}

template<int N_IN, int D, int R>
__global__ __launch_bounds__(128)
void conv_layer(const float* __restrict__ buf, float* __restrict__ outp,
                const float* __restrict__ wgt, const float* __restrict__ bias,
                int layer) {
    __shared__ u64 ws2[N_IN * 9];
    __shared__ u64 bsh;
    int tid = threadIdx.x;
    for (int i = tid; i < N_IN * 9; i += 128)
        ws2[i] = pack2(wgt[i], wgt[N_IN * 9 + i]);   // pack (oc0, oc1) weight pair
    if (tid == 0) bsh = pack2(bias[2 * layer], bias[2 * layer + 1]);
    __syncthreads();

    int w  = blockIdx.x * 128 + tid;
    int r0 = blockIdx.y * R;
    int b  = blockIdx.z;
    u64 bias2 = bsh;

    bool interior = (r0 >= D) && (r0 + R + D <= Hdim);
    if (interior) conv_body<N_IN, D, R, false>(buf, outp, ws2, bias2, b, r0, w);
    else          conv_body<N_IN, D, R, true >(buf, outp, ws2, bias2, b, r0, w);
}

// Copy x (4,1,512,512) into channel 0 of the 25-channel output buffer.
__global__ void copy_in_kernel(const float4* __restrict__ x, float4* __restrict__ out) {
    int idx = blockIdx.x * blockDim.x + threadIdx.x;      // over B*CS/4
    const int P4 = CS / 4;
    if (idx >= Bdim * P4) return;
    int b = idx / P4;
    int p = idx - b * P4;
    out[(size_t)b * (C_TOTAL * P4) + p] = x[idx];
}

extern "C" void kernel_launch(void* const* d_in, const int* in_sizes, int n_in,
                              void* d_out, int out_size) {
    const float* x    = (const float*)d_in[0];
    const float* bias = (const float*)d_in[1];
    float* out = (float*)d_out;

    {
        int total4 = Bdim * CS / 4;
        copy_in_kernel<<<(total4 + 255) / 256, 256>>>((const float4*)x, (float4*)out);
    }

    // R: 16 for small dilation (better occupancy), 32 for large dilation
    // (lower (R+2D)/R halo redundancy on the heavy layers).
#define LAYER(i, NIN, DD, RR) \
    conv_layer<NIN, DD, RR><<<dim3(Wdim / 128, Hdim / RR, Bdim), 128>>>( \
        out, out, (const float*)d_in[2 + (i)], bias, (i))

    LAYER(0,  1,  1, 16);
    LAYER(1,  3,  2, 16);
    LAYER(2,  5,  3, 16);
    LAYER(3,  7,  4, 16);
    LAYER(4,  9,  5, 32);
    LAYER(5,  11, 6, 32);
    LAYER(6,  13, 7, 32);
    LAYER(7,  15, 8, 32);
    LAYER(8,  17, 9, 32);
    LAYER(9,  19, 10, 32);
    LAYER(10, 21, 11, 32);
    LAYER(11, 23, 12, 32);
#undef LAYER
}